// round 2
// baseline (speedup 1.0000x reference)
#include <cuda_runtime.h>
#include <math.h>

#define BATCH 2
#define AG    5
#define PR    4              // A-1
#define NPAIR 40             // B*A*(A-1)
#define NIMG  10             // B*A
#define HH    128
#define WWID  128
#define HW    16384
#define C64   64
#define CIN   128
#define COUT  192

// Scratch (device globals: allocation-free rule)
__device__ float g_catA[NIMG * HW * CIN];      // NHWC: [img][px][128ch] ch0..63=feats, 64..127=mean
__device__ float g_catB[NIMG * HW * CIN];
__device__ float g_frot[NPAIR * HW * C64];     // rotated maps per (b,i,j) pair, NHWC
__device__ float g_gx[NIMG * HW * COUT];       // conv output (pre-gating)
__device__ float g_w2[9 * CIN * COUT];         // weights re-laid-out [kxy][ic][oc]

// --------------------------------------------------------------------------
// bilinear corner computation, replicating reference semantics exactly:
// floor, frac weights, per-corner float validity in [0,127], clamp for gather
__device__ __forceinline__ void corners(float x, float y,
    int &xi0, int &xi1, int &yi0, int &yi1,
    float &w00, float &w10, float &w01, float &w11)
{
    float x0f = floorf(x), y0f = floorf(y);
    float fx = x - x0f, fy = y - y0f;
    float x1f = x0f + 1.0f, y1f = y0f + 1.0f;
    float vx0 = (x0f >= 0.0f && x0f <= 127.0f) ? 1.0f : 0.0f;
    float vx1 = (x1f >= 0.0f && x1f <= 127.0f) ? 1.0f : 0.0f;
    float vy0 = (y0f >= 0.0f && y0f <= 127.0f) ? 1.0f : 0.0f;
    float vy1 = (y1f >= 0.0f && y1f <= 127.0f) ? 1.0f : 0.0f;
    float wx0 = 1.0f - fx, wx1 = fx, wy0 = 1.0f - fy, wy1 = fy;
    w00 = wx0 * wy0 * vx0 * vy0;
    w10 = wx1 * wy0 * vx1 * vy0;
    w01 = wx0 * wy1 * vx0 * vy1;
    w11 = wx1 * wy1 * vx1 * vy1;
    xi0 = min(max((int)x0f, 0), 127);
    xi1 = min(max((int)x1f, 0), 127);
    yi0 = min(max((int)y0f, 0), 127);
    yi1 = min(max((int)y1f, 0), 127);
}

// --------------------------------------------------------------------------
// NCHW (input feats) -> NHWC into catA channels [0,64)
__global__ void k_transpose(const float* __restrict__ feats)
{
    __shared__ float sm[64][65];
    int img = blockIdx.y;
    int px0 = blockIdx.x * 64;
    int tid = threadIdx.x;  // 256
    const float* src = feats + img * C64 * HW;
    #pragma unroll
    for (int k = 0; k < 16; k++) {
        int c = k * 4 + (tid >> 6);
        int p = tid & 63;
        sm[c][p] = src[c * HW + px0 + p];
    }
    __syncthreads();
    float* dst = g_catA + (img * HW + px0) * CIN;
    #pragma unroll
    for (int k = 0; k < 16; k++) {
        int p = k * 4 + (tid >> 6);
        int c = tid & 63;
        dst[p * CIN + c] = sm[c][p];
    }
}

// wx [oc][ic][ky][kx] -> g_w2 [(ky*3+kx)*128 + ic]*192 + oc
__global__ void k_weights(const float* __restrict__ wx)
{
    int idx = blockIdx.x * 256 + threadIdx.x;
    if (idx >= 9 * CIN * COUT) return;
    int oc  = idx % COUT;
    int t   = idx / COUT;
    int ic  = t % CIN;
    int kxy = t / CIN;
    g_w2[idx] = wx[(oc * CIN + ic) * 9 + kxy];
}

// --------------------------------------------------------------------------
// Pass 1: rotation resample. One thread = one pixel of one pair, all 64 ch via float4.
__global__ void k_rotate(const float* __restrict__ trans, int srcSel)
{
    const float* cat = srcSel ? g_catB : g_catA;
    int p  = blockIdx.x;
    int b  = p / (AG * PR);
    int r  = p % (AG * PR);
    int i  = r / PR;
    int jj = r % PR;
    int j  = jj + (jj >= i ? 1 : 0);
    const float* t = trans + ((b * AG + i) * AG + j) * 16;
    float t00 = t[0], t01 = t[1], t10 = t[4], t11 = t[5];

    int px = blockIdx.y * 256 + threadIdx.x;
    int h = px >> 7, w = px & 127;
    float xs = (float)(2 * w + 1) * 0.0078125f - 1.0f;
    float ys = (float)(2 * h + 1) * 0.0078125f - 1.0f;
    float g0 = t00 * xs + t01 * ys;
    float g1 = t10 * xs + t11 * ys;
    float x = ((g0 + 1.0f) * 128.0f - 1.0f) * 0.5f;
    float y = ((g1 + 1.0f) * 128.0f - 1.0f) * 0.5f;

    int xi0, xi1, yi0, yi1; float w00, w10, w01, w11;
    corners(x, y, xi0, xi1, yi0, yi1, w00, w10, w01, w11);

    const float* base = cat + (b * AG + j) * HW * CIN;
    const float* p00 = base + (yi0 * 128 + xi0) * CIN;
    const float* p10 = base + (yi0 * 128 + xi1) * CIN;
    const float* p01 = base + (yi1 * 128 + xi0) * CIN;
    const float* p11 = base + (yi1 * 128 + xi1) * CIN;
    float* out = g_frot + (p * HW + px) * C64;
    #pragma unroll
    for (int c4 = 0; c4 < 16; c4++) {
        float4 a  = *(const float4*)(p00 + c4 * 4);
        float4 bb = *(const float4*)(p10 + c4 * 4);
        float4 cc = *(const float4*)(p01 + c4 * 4);
        float4 dd = *(const float4*)(p11 + c4 * 4);
        float4 o;
        o.x = w00 * a.x + w10 * bb.x + w01 * cc.x + w11 * dd.x;
        o.y = w00 * a.y + w10 * bb.y + w01 * cc.y + w11 * dd.y;
        o.z = w00 * a.z + w10 * bb.z + w01 * cc.z + w11 * dd.z;
        o.w = w00 * a.w + w10 * bb.w + w01 * cc.w + w11 * dd.w;
        *(float4*)(out + c4 * 4) = o;
    }
}

// --------------------------------------------------------------------------
// Pass 2: translation resample of frot + mean over j != i  -> cat[...,64:128]
__global__ void k_translate(const float* __restrict__ trans, int sel)
{
    float* cat = sel ? g_catB : g_catA;
    int bi = blockIdx.x;          // b*AG + i
    int i  = bi % AG;
    int px = blockIdx.y * 256 + threadIdx.x;
    int h = px >> 7, w = px & 127;
    float xsv = (float)(2 * w + 1) * 0.0078125f - 1.0f;
    float ysv = (float)(2 * h + 1) * 0.0078125f - 1.0f;

    int offs[16];
    float wgt[16];
    #pragma unroll
    for (int jj = 0; jj < PR; jj++) {
        int j = jj + (jj >= i ? 1 : 0);
        const float* t = trans + (bi * AG + j) * 16;
        float xtr = (4.0f * t[3]) * 0.0078125f;
        float ytr = -(4.0f * t[7]) * 0.0078125f;
        float x = ((xsv + xtr + 1.0f) * 128.0f - 1.0f) * 0.5f;
        float y = ((ysv + ytr + 1.0f) * 128.0f - 1.0f) * 0.5f;
        int xi0, xi1, yi0, yi1; float w00, w10, w01, w11;
        corners(x, y, xi0, xi1, yi0, yi1, w00, w10, w01, w11);
        int pb = (bi * PR + jj) * HW;
        offs[jj * 4 + 0] = (pb + yi0 * 128 + xi0) * C64; wgt[jj * 4 + 0] = w00;
        offs[jj * 4 + 1] = (pb + yi0 * 128 + xi1) * C64; wgt[jj * 4 + 1] = w10;
        offs[jj * 4 + 2] = (pb + yi1 * 128 + xi0) * C64; wgt[jj * 4 + 2] = w01;
        offs[jj * 4 + 3] = (pb + yi1 * 128 + xi1) * C64; wgt[jj * 4 + 3] = w11;
    }

    float* out = cat + (bi * HW + px) * CIN + C64;
    #pragma unroll
    for (int c4 = 0; c4 < 16; c4++) {
        float ax = 0.f, ay = 0.f, az = 0.f, aw = 0.f;
        #pragma unroll
        for (int s = 0; s < 16; s++) {
            float4 v = *(const float4*)(g_frot + offs[s] + c4 * 4);
            ax += wgt[s] * v.x; ay += wgt[s] * v.y;
            az += wgt[s] * v.z; aw += wgt[s] * v.w;
        }
        float4 o = make_float4(ax * 0.25f, ay * 0.25f, az * 0.25f, aw * 0.25f);
        *(float4*)(out + c4 * 4) = o;
    }
}

// --------------------------------------------------------------------------
// 3x3 conv, NHWC implicit GEMM, fp32.  Tile: 8 rows x 16 cols, 96 oc per block.
// Thread: 8 px (one column) x 6 oc = 48 accumulators. ic chunked by 8.
__global__ void __launch_bounds__(256, 2) k_conv(int sel)
{
    const float* cat = sel ? g_catB : g_catA;
    __shared__ float sp[8 * 10 * 18];   // [ic8][row10][col18]
    __shared__ float sw[9 * 8 * 96];    // [kxy][ic8][oc96]

    int tilex = blockIdx.x & 7;         // 8 col tiles
    int tiley = blockIdx.x >> 3;        // 16 row tiles
    int img   = blockIdx.y;
    int ocg   = blockIdx.z;             // 0/1 -> oc base 0/96
    int col0 = tilex * 16, row0 = tiley * 8;
    int tid = threadIdx.x;
    int oct = tid >> 4;                 // 0..15
    int pxt = tid & 15;                 // 0..15 (column within tile)

    float acc[8][6];
    #pragma unroll
    for (int k = 0; k < 8; k++)
        #pragma unroll
        for (int o = 0; o < 6; o++) acc[k][o] = 0.0f;

    const float* imgbase = cat + img * HW * CIN;

    for (int icc = 0; icc < 16; icc++) {
        int ic0 = icc * 8;
        __syncthreads();
        // fill input patch: 10x18 positions x 8 ch (2 float4 each) = 360 float4
        for (int idx = tid; idx < 360; idx += 256) {
            int g  = idx & 1;
            int rc = idx >> 1;
            int rr = rc / 18, cc2 = rc % 18;
            int gy = row0 - 1 + rr, gxc = col0 - 1 + cc2;
            float4 v = make_float4(0.f, 0.f, 0.f, 0.f);
            if (gy >= 0 && gy < 128 && gxc >= 0 && gxc < 128)
                v = *(const float4*)(imgbase + (gy * 128 + gxc) * CIN + ic0 + g * 4);
            int sb = rr * 18 + cc2;
            sp[(g * 4 + 0) * 180 + sb] = v.x;
            sp[(g * 4 + 1) * 180 + sb] = v.y;
            sp[(g * 4 + 2) * 180 + sb] = v.z;
            sp[(g * 4 + 3) * 180 + sb] = v.w;
        }
        // fill weights: 9 kxy x 8 ic x 96 oc = 1728 float4
        for (int idx = tid; idx < 1728; idx += 256) {
            int kxy = idx / 192;
            int rem = idx % 192;
            int ic  = rem / 24;
            int oq  = rem % 24;
            float4 v = *(const float4*)(g_w2 + (kxy * CIN + ic0 + ic) * COUT + ocg * 96 + oq * 4);
            *(float4*)(sw + (kxy * 8 + ic) * 96 + oq * 4) = v;
        }
        __syncthreads();

        for (int ic = 0; ic < 8; ic++) {
            #pragma unroll
            for (int kx = 0; kx < 3; kx++) {
                float rv[10];
                #pragma unroll
                for (int rr = 0; rr < 10; rr++)
                    rv[rr] = sp[ic * 180 + rr * 18 + pxt + kx];
                #pragma unroll
                for (int ky = 0; ky < 3; ky++) {
                    float wv[6];
                    #pragma unroll
                    for (int o = 0; o < 6; o++)
                        wv[o] = sw[((ky * 3 + kx) * 8 + ic) * 96 + oct * 6 + o];
                    #pragma unroll
                    for (int k = 0; k < 8; k++)
                        #pragma unroll
                        for (int o = 0; o < 6; o++)
                            acc[k][o] += rv[k + ky] * wv[o];
                }
            }
        }
    }

    #pragma unroll
    for (int k = 0; k < 8; k++) {
        float* op = g_gx + (img * HW + (row0 + k) * 128 + col0 + pxt) * COUT + ocg * 96 + oct * 6;
        #pragma unroll
        for (int o = 0; o < 6; o++) op[o] = acc[k][o];
    }
}

// --------------------------------------------------------------------------
// GRU gating (h0 = 0): r=sig(xr+br), z=sig(xz+bz), n=tanh(xn + r*bn), out=(1-z)*n
__global__ void k_gru(const float* __restrict__ bx, const float* __restrict__ bh,
                      int dstSel, float* __restrict__ out_nchw)
{
    int idx = blockIdx.x * 256 + threadIdx.x;  // NIMG*HW*64
    int c = idx & 63;
    int t = idx >> 6;          // img*HW + px
    int px  = t & (HW - 1);
    int img = t >> 14;
    const float* g = g_gx + t * COUT;
    float xr = g[c]       + bx[c]       + bh[c];
    float xz = g[64 + c]  + bx[64 + c]  + bh[64 + c];
    float xn = g[128 + c] + bx[128 + c];
    float rr = 1.0f / (1.0f + expf(-xr));
    float zz = 1.0f / (1.0f + expf(-xz));
    float nn = tanhf(xn + rr * bh[128 + c]);
    float o = (1.0f - zz) * nn;
    if (out_nchw) {
        out_nchw[(img * C64 + c) * HW + px] = o;
    } else {
        float* cat = dstSel ? g_catB : g_catA;
        cat[t * CIN + c] = o;
    }
}

// --------------------------------------------------------------------------
extern "C" void kernel_launch(void* const* d_in, const int* in_sizes, int n_in,
                              void* d_out, int out_size)
{
    const float* feats = (const float*)d_in[0];
    const float* trans = (const float*)d_in[1];
    const float* wx    = (const float*)d_in[2];
    // d_in[3] = wh (unused: h0 = 0 kills hidden convs; only bh survives)
    const float* bx    = (const float*)d_in[4];
    const float* bh    = (const float*)d_in[5];
    float* out = (float*)d_out;

    k_transpose<<<dim3(256, NIMG), 256>>>(feats);
    k_weights<<<(9 * CIN * COUT + 255) / 256, 256>>>(wx);

    // iteration 1: src = catA, new feats -> catB
    k_rotate   <<<dim3(NPAIR, 64), 256>>>(trans, 0);
    k_translate<<<dim3(NIMG, 64), 256>>>(trans, 0);
    k_conv     <<<dim3(128, NIMG, 2), 256>>>(0);
    k_gru      <<<(NIMG * HW * C64) / 256, 256>>>(bx, bh, 1, nullptr);

    // iteration 2: src = catB, final feats -> d_out (NCHW)
    k_rotate   <<<dim3(NPAIR, 64), 256>>>(trans, 1);
    k_translate<<<dim3(NIMG, 64), 256>>>(trans, 1);
    k_conv     <<<dim3(128, NIMG, 2), 256>>>(1);
    k_gru      <<<(NIMG * HW * C64) / 256, 256>>>(bx, bh, 0, out);
}

// round 8
// speedup vs baseline: 1.2008x; 1.2008x over previous
#include <cuda_runtime.h>
#include <cuda_bf16.h>
#include <math.h>
#include <stdint.h>

#define BATCH 2
#define AG    5
#define PR    4
#define NPAIR 40
#define NIMG  10
#define HW    16384
#define C64   64
#define CIN   128
#define COUT  192

// Scratch (device globals: allocation-free rule)
__device__ float g_catA[NIMG * HW * CIN];     // NHWC fp32: ch0..63 feats, 64..127 mean
__device__ float g_catB[NIMG * HW * CIN];
__device__ float g_frot[NPAIR * HW * C64];    // rotated maps, NHWC
__device__ float g_gx[NIMG * HW * COUT];      // raw conv output (pre-gating)
__device__ __nv_bfloat16 g_ch[NIMG * HW * CIN];   // bf16 hi split of cat
__device__ __nv_bfloat16 g_cl[NIMG * HW * CIN];   // bf16 lo split of cat
__device__ __nv_bfloat16 g_wbh[9 * COUT * CIN];   // weights hi [tap][oc][ic]
__device__ __nv_bfloat16 g_wbl[9 * COUT * CIN];   // weights lo

// ===================== mma.sync helpers (baseline PTX, sm_80+) ============
__device__ __forceinline__ uint32_t smem_u32(const void* p) {
    uint32_t a;
    asm("{ .reg .u64 t; cvta.to.shared.u64 t, %1; cvt.u32.u64 %0, t; }" : "=r"(a) : "l"(p));
    return a;
}
__device__ __forceinline__ void ldsm4(uint32_t* r, uint32_t a) {
    asm volatile("ldmatrix.sync.aligned.m8n8.x4.shared.b16 {%0,%1,%2,%3}, [%4];"
        : "=r"(r[0]), "=r"(r[1]), "=r"(r[2]), "=r"(r[3]) : "r"(a));
}
__device__ __forceinline__ void mma16816(float* d, const uint32_t* a, const uint32_t* b) {
    asm volatile("mma.sync.aligned.m16n8k16.row.col.f32.bf16.bf16.f32 "
        "{%0,%1,%2,%3}, {%4,%5,%6,%7}, {%8,%9}, {%0,%1,%2,%3};"
        : "+f"(d[0]), "+f"(d[1]), "+f"(d[2]), "+f"(d[3])
        : "r"(a[0]), "r"(a[1]), "r"(a[2]), "r"(a[3]), "r"(b[0]), "r"(b[1]));
}

// ===================== warp-stage kernels (unchanged, passing) ============
__device__ __forceinline__ void corners(float x, float y,
    int &xi0, int &xi1, int &yi0, int &yi1,
    float &w00, float &w10, float &w01, float &w11)
{
    float x0f = floorf(x), y0f = floorf(y);
    float fx = x - x0f, fy = y - y0f;
    float x1f = x0f + 1.0f, y1f = y0f + 1.0f;
    float vx0 = (x0f >= 0.0f && x0f <= 127.0f) ? 1.0f : 0.0f;
    float vx1 = (x1f >= 0.0f && x1f <= 127.0f) ? 1.0f : 0.0f;
    float vy0 = (y0f >= 0.0f && y0f <= 127.0f) ? 1.0f : 0.0f;
    float vy1 = (y1f >= 0.0f && y1f <= 127.0f) ? 1.0f : 0.0f;
    float wx0 = 1.0f - fx, wx1 = fx, wy0 = 1.0f - fy, wy1 = fy;
    w00 = wx0 * wy0 * vx0 * vy0;
    w10 = wx1 * wy0 * vx1 * vy0;
    w01 = wx0 * wy1 * vx0 * vy1;
    w11 = wx1 * wy1 * vx1 * vy1;
    xi0 = min(max((int)x0f, 0), 127);
    xi1 = min(max((int)x1f, 0), 127);
    yi0 = min(max((int)y0f, 0), 127);
    yi1 = min(max((int)y1f, 0), 127);
}

__global__ void k_transpose(const float* __restrict__ feats)
{
    __shared__ float sm[64][65];
    int img = blockIdx.y;
    int px0 = blockIdx.x * 64;
    int tid = threadIdx.x;
    const float* src = feats + img * C64 * HW;
    #pragma unroll
    for (int k = 0; k < 16; k++) {
        int c = k * 4 + (tid >> 6);
        int p = tid & 63;
        sm[c][p] = src[c * HW + px0 + p];
    }
    __syncthreads();
    float* dst = g_catA + (img * HW + px0) * CIN;
    #pragma unroll
    for (int k = 0; k < 16; k++) {
        int p = k * 4 + (tid >> 6);
        int c = tid & 63;
        dst[p * CIN + c] = sm[c][p];
    }
}

__global__ void k_rotate(const float* __restrict__ trans, int srcSel)
{
    const float* cat = srcSel ? g_catB : g_catA;
    int p  = blockIdx.x;
    int b  = p / (AG * PR);
    int r  = p % (AG * PR);
    int i  = r / PR;
    int jj = r % PR;
    int j  = jj + (jj >= i ? 1 : 0);
    const float* t = trans + ((b * AG + i) * AG + j) * 16;
    float t00 = t[0], t01 = t[1], t10 = t[4], t11 = t[5];

    int px = blockIdx.y * 256 + threadIdx.x;
    int h = px >> 7, w = px & 127;
    float xs = (float)(2 * w + 1) * 0.0078125f - 1.0f;
    float ys = (float)(2 * h + 1) * 0.0078125f - 1.0f;
    float g0 = t00 * xs + t01 * ys;
    float g1 = t10 * xs + t11 * ys;
    float x = ((g0 + 1.0f) * 128.0f - 1.0f) * 0.5f;
    float y = ((g1 + 1.0f) * 128.0f - 1.0f) * 0.5f;

    int xi0, xi1, yi0, yi1; float w00, w10, w01, w11;
    corners(x, y, xi0, xi1, yi0, yi1, w00, w10, w01, w11);

    const float* base = cat + (b * AG + j) * HW * CIN;
    const float* p00 = base + (yi0 * 128 + xi0) * CIN;
    const float* p10 = base + (yi0 * 128 + xi1) * CIN;
    const float* p01 = base + (yi1 * 128 + xi0) * CIN;
    const float* p11 = base + (yi1 * 128 + xi1) * CIN;
    float* out = g_frot + (p * HW + px) * C64;
    #pragma unroll
    for (int c4 = 0; c4 < 16; c4++) {
        float4 a  = *(const float4*)(p00 + c4 * 4);
        float4 bb = *(const float4*)(p10 + c4 * 4);
        float4 cc = *(const float4*)(p01 + c4 * 4);
        float4 dd = *(const float4*)(p11 + c4 * 4);
        float4 o;
        o.x = w00 * a.x + w10 * bb.x + w01 * cc.x + w11 * dd.x;
        o.y = w00 * a.y + w10 * bb.y + w01 * cc.y + w11 * dd.y;
        o.z = w00 * a.z + w10 * bb.z + w01 * cc.z + w11 * dd.z;
        o.w = w00 * a.w + w10 * bb.w + w01 * cc.w + w11 * dd.w;
        *(float4*)(out + c4 * 4) = o;
    }
}

__global__ void k_translate(const float* __restrict__ trans, int sel)
{
    float* cat = sel ? g_catB : g_catA;
    int bi = blockIdx.x;
    int i  = bi % AG;
    int px = blockIdx.y * 256 + threadIdx.x;
    int h = px >> 7, w = px & 127;
    float xsv = (float)(2 * w + 1) * 0.0078125f - 1.0f;
    float ysv = (float)(2 * h + 1) * 0.0078125f - 1.0f;

    int offs[16];
    float wgt[16];
    #pragma unroll
    for (int jj = 0; jj < PR; jj++) {
        int j = jj + (jj >= i ? 1 : 0);
        const float* t = trans + (bi * AG + j) * 16;
        float xtr = (4.0f * t[3]) * 0.0078125f;
        float ytr = -(4.0f * t[7]) * 0.0078125f;
        float x = ((xsv + xtr + 1.0f) * 128.0f - 1.0f) * 0.5f;
        float y = ((ysv + ytr + 1.0f) * 128.0f - 1.0f) * 0.5f;
        int xi0, xi1, yi0, yi1; float w00, w10, w01, w11;
        corners(x, y, xi0, xi1, yi0, yi1, w00, w10, w01, w11);
        int pb = (bi * PR + jj) * HW;
        offs[jj * 4 + 0] = (pb + yi0 * 128 + xi0) * C64; wgt[jj * 4 + 0] = w00;
        offs[jj * 4 + 1] = (pb + yi0 * 128 + xi1) * C64; wgt[jj * 4 + 1] = w10;
        offs[jj * 4 + 2] = (pb + yi1 * 128 + xi0) * C64; wgt[jj * 4 + 2] = w01;
        offs[jj * 4 + 3] = (pb + yi1 * 128 + xi1) * C64; wgt[jj * 4 + 3] = w11;
    }

    float* out = cat + (bi * HW + px) * CIN + C64;
    #pragma unroll
    for (int c4 = 0; c4 < 16; c4++) {
        float ax = 0.f, ay = 0.f, az = 0.f, aw = 0.f;
        #pragma unroll
        for (int s = 0; s < 16; s++) {
            float4 v = *(const float4*)(g_frot + offs[s] + c4 * 4);
            ax += wgt[s] * v.x; ay += wgt[s] * v.y;
            az += wgt[s] * v.z; aw += wgt[s] * v.w;
        }
        float4 o = make_float4(ax * 0.25f, ay * 0.25f, az * 0.25f, aw * 0.25f);
        *(float4*)(out + c4 * 4) = o;
    }
}

// ===================== bf16 split passes ==================================
__global__ void k_split(int sel)
{
    const float* cat = sel ? g_catB : g_catA;
    int idx = (blockIdx.x * 256 + threadIdx.x) * 4;
    float4 v = *(const float4*)(cat + idx);
    float hx = __bfloat162float(__float2bfloat16_rn(v.x));
    float hy = __bfloat162float(__float2bfloat16_rn(v.y));
    float hz = __bfloat162float(__float2bfloat16_rn(v.z));
    float hw = __bfloat162float(__float2bfloat16_rn(v.w));
    *(__nv_bfloat162*)(g_ch + idx)     = __floats2bfloat162_rn(hx, hy);
    *(__nv_bfloat162*)(g_ch + idx + 2) = __floats2bfloat162_rn(hz, hw);
    *(__nv_bfloat162*)(g_cl + idx)     = __floats2bfloat162_rn(v.x - hx, v.y - hy);
    *(__nv_bfloat162*)(g_cl + idx + 2) = __floats2bfloat162_rn(v.z - hz, v.w - hw);
}

__global__ void k_wsplit(const float* __restrict__ wx)
{
    int idx = blockIdx.x * 256 + threadIdx.x;
    if (idx >= 9 * COUT * CIN) return;
    int ic  = idx % CIN;
    int t   = idx / CIN;
    int oc  = t % COUT;
    int tap = t / COUT;
    float v = wx[(oc * CIN + ic) * 9 + tap];
    float h = __bfloat162float(__float2bfloat16_rn(v));
    g_wbh[(tap * COUT + oc) * CIN + ic] = __float2bfloat16_rn(v);
    g_wbl[(tap * COUT + oc) * CIN + ic] = __float2bfloat16_rn(v - h);
}

// ===================== mma.sync implicit-GEMM conv ========================
// CTA: one image row h (128 px) x 96 oc (blockIdx.z). D[128,96] in registers.
// A tile: padded 130 rows (px -1..128) x 128 ic bf16, hi+lo. Reloaded per ky.
// B tile: 96 oc x 128 ic bf16, hi+lo. Reloaded per tap.
// 16B-chunk XOR swizzle: phys = chunk ^ (row & 15) -> conflict-free ldmatrix.
#define SM_AH 0
#define SM_AL 33792
#define SM_BH 67584
#define SM_BL 92160
#define SM_TOTAL 116736

__global__ void __launch_bounds__(256, 1) k_convmma(int sel)
{
    extern __shared__ char smem[];
    uint32_t sb = smem_u32(smem);
    const uint32_t sAH = sb + SM_AH, sAL = sb + SM_AL;
    const uint32_t sBH = sb + SM_BH, sBL = sb + SM_BL;

    int h   = blockIdx.x;
    int img = blockIdx.y;
    int z   = blockIdx.z;            // oc half: 0 -> 0..95, 1 -> 96..191
    int tid = threadIdx.x;
    int wid = tid >> 5, lane = tid & 31;
    int mrow = wid & 3;              // 32-px group
    int ncol = wid >> 2;             // 48-oc group

    const __nv_bfloat16* ch = g_ch;
    const __nv_bfloat16* cl = g_cl;

    float acc[2][6][4];
    #pragma unroll
    for (int mi = 0; mi < 2; mi++)
        #pragma unroll
        for (int ni = 0; ni < 6; ni++)
            #pragma unroll
            for (int k = 0; k < 4; k++) acc[mi][ni][k] = 0.0f;

    // per-lane B row indices (constant across taps)
    int brow[3];
    #pragma unroll
    for (int t = 0; t < 3; t++)
        brow[t] = ncol * 48 + t * 16 + ((lane >> 4) << 3) + (lane & 7);

    for (int ky = 0; ky < 3; ky++) {
        int py = h - 1 + ky;
        if (py < 0 || py > 127) continue;

        __syncthreads();
        // fill A (hi+lo): 130 rows x 16 chunks, zero pad rows 0 and 129
        {
            const uint4* Ah4 = (const uint4*)(ch + (img * HW + py * 128) * CIN);
            const uint4* Al4 = (const uint4*)(cl + (img * HW + py * 128) * CIN);
            for (int idx = tid; idx < 4160; idx += 256) {
                int s = idx >= 2080;
                int r = s ? idx - 2080 : idx;
                int p = r >> 4, c = r & 15;
                int px = p - 1;
                uint4 v = make_uint4(0u, 0u, 0u, 0u);
                if (px >= 0 && px < 128) v = (s ? Al4 : Ah4)[px * 16 + c];
                uint32_t off = (uint32_t)p * 256u + (uint32_t)((c ^ (p & 15)) << 4);
                *(uint4*)(smem + (s ? SM_AL : SM_AH) + off) = v;
            }
        }

        for (int kx = 0; kx < 3; kx++) {
            int tap = ky * 3 + kx;
            __syncthreads();   // prior mma done before overwriting B (and A ready)
            {
                const uint4* Bh4 = (const uint4*)(g_wbh + (tap * COUT + z * 96) * CIN);
                const uint4* Bl4 = (const uint4*)(g_wbl + (tap * COUT + z * 96) * CIN);
                for (int idx = tid; idx < 3072; idx += 256) {
                    int s = idx >= 1536;
                    int r = s ? idx - 1536 : idx;
                    int oc = r >> 4, c = r & 15;
                    uint4 v = (s ? Bl4 : Bh4)[oc * 16 + c];
                    uint32_t off = (uint32_t)oc * 256u + (uint32_t)((c ^ (oc & 15)) << 4);
                    *(uint4*)(smem + (s ? SM_BL : SM_BH) + off) = v;
                }
            }
            __syncthreads();

            int arow0 = mrow * 32 + kx + (lane & 15);  // padded-row index, mi=0
            #pragma unroll
            for (int ks = 0; ks < 8; ks++) {
                uint32_t Ah[2][4], Al[2][4], Bh[3][4], Bl[3][4];
                int ca = 2 * ks + (lane >> 4);
                #pragma unroll
                for (int mi = 0; mi < 2; mi++) {
                    int ar = arow0 + mi * 16;
                    uint32_t off = (uint32_t)ar * 256u + (uint32_t)(((ca ^ (ar & 15))) << 4);
                    ldsm4(Ah[mi], sAH + off);
                    ldsm4(Al[mi], sAL + off);
                }
                int cb = 2 * ks + ((lane >> 3) & 1);
                #pragma unroll
                for (int t = 0; t < 3; t++) {
                    uint32_t off = (uint32_t)brow[t] * 256u + (uint32_t)(((cb ^ (brow[t] & 15))) << 4);
                    ldsm4(Bh[t], sBH + off);
                    ldsm4(Bl[t], sBL + off);
                }
                #pragma unroll
                for (int mi = 0; mi < 2; mi++)
                    #pragma unroll
                    for (int t = 0; t < 3; t++)
                        #pragma unroll
                        for (int hf = 0; hf < 2; hf++) {
                            float* d = acc[mi][2 * t + hf];
                            mma16816(d, Ah[mi], &Bh[t][2 * hf]);
                            mma16816(d, Al[mi], &Bh[t][2 * hf]);
                            mma16816(d, Ah[mi], &Bl[t][2 * hf]);
                        }
            }
        }
    }

    // store raw conv out to g_gx [img][px][192]
    int imgrow = img * HW + h * 128;
    #pragma unroll
    for (int mi = 0; mi < 2; mi++) {
        int x0 = mrow * 32 + mi * 16 + (lane >> 2);
        #pragma unroll
        for (int ni = 0; ni < 6; ni++) {
            int oc = z * 96 + ncol * 48 + ni * 8 + (lane & 3) * 2;
            float* o0 = g_gx + (imgrow + x0) * COUT + oc;
            float* o1 = g_gx + (imgrow + x0 + 8) * COUT + oc;
            *(float2*)o0 = make_float2(acc[mi][ni][0], acc[mi][ni][1]);
            *(float2*)o1 = make_float2(acc[mi][ni][2], acc[mi][ni][3]);
        }
    }
    (void)sel;
}

// ===================== GRU gating (validated in R1) =======================
__global__ void k_gru(const float* __restrict__ bx, const float* __restrict__ bh,
                      int dstSel, float* __restrict__ out_nchw)
{
    int idx = blockIdx.x * 256 + threadIdx.x;  // NIMG*HW*64
    int c = idx & 63;
    int t = idx >> 6;
    int px  = t & (HW - 1);
    int img = t >> 14;
    const float* g = g_gx + t * COUT;
    float xr = g[c]       + bx[c]       + bh[c];
    float xz = g[64 + c]  + bx[64 + c]  + bh[64 + c];
    float xn = g[128 + c] + bx[128 + c];
    float rr = 1.0f / (1.0f + expf(-xr));
    float zz = 1.0f / (1.0f + expf(-xz));
    float nn = tanhf(xn + rr * bh[128 + c]);
    float o = (1.0f - zz) * nn;
    if (out_nchw) {
        out_nchw[(img * C64 + c) * HW + px] = o;
    } else {
        float* cat = dstSel ? g_catB : g_catA;
        cat[t * CIN + c] = o;
    }
}

// ==========================================================================
extern "C" void kernel_launch(void* const* d_in, const int* in_sizes, int n_in,
                              void* d_out, int out_size)
{
    (void)in_sizes; (void)n_in; (void)out_size;
    const float* feats = (const float*)d_in[0];
    const float* trans = (const float*)d_in[1];
    const float* wx    = (const float*)d_in[2];
    const float* bx    = (const float*)d_in[4];
    const float* bh    = (const float*)d_in[5];
    float* out = (float*)d_out;

    cudaFuncSetAttribute(k_convmma, cudaFuncAttributeMaxDynamicSharedMemorySize, SM_TOTAL);

    k_transpose<<<dim3(256, NIMG), 256>>>(feats);
    k_wsplit<<<(9 * COUT * CIN + 255) / 256, 256>>>(wx);

    // iteration 1: src catA -> new feats into catB
    k_rotate   <<<dim3(NPAIR, 64), 256>>>(trans, 0);
    k_translate<<<dim3(NIMG, 64), 256>>>(trans, 0);
    k_split    <<<NIMG * HW * CIN / 1024, 256>>>(0);
    k_convmma  <<<dim3(128, NIMG, 2), 256, SM_TOTAL>>>(0);
    k_gru      <<<(NIMG * HW * C64) / 256, 256>>>(bx, bh, 1, nullptr);

    // iteration 2: src catB -> final output (NCHW)
    k_rotate   <<<dim3(NPAIR, 64), 256>>>(trans, 1);
    k_translate<<<dim3(NIMG, 64), 256>>>(trans, 1);
    k_split    <<<NIMG * HW * CIN / 1024, 256>>>(1);
    k_convmma  <<<dim3(128, NIMG, 2), 256, SM_TOTAL>>>(1);
    k_gru      <<<(NIMG * HW * C64) / 256, 256>>>(bx, bh, 0, out);
}

// round 10
// speedup vs baseline: 3.1387x; 2.6138x over previous
#include <cuda_runtime.h>
#include <cuda_bf16.h>
#include <math.h>
#include <stdint.h>

#define BATCH 2
#define AG    5
#define PR    4
#define NPAIR 40
#define NIMG  10
#define HW    16384
#define C64   64
#define CIN   128
#define COUT  192

// ---- padded conv layouts ----
// A source rows: per (img, py): 128 px * 272B (128 bf16ch*2B + 16B pad) = 34816B
#define AROWB   272
#define AIMGROW 34816
// B stages: 18 = 9 taps * 2 k-halves; per stage: [hi|lo] x 192 oc x 144B row
#define BROWB   144
#define BSPLIT  27648
#define BSTAGE  55296

// Scratch (device globals: allocation-free rule; zero-initialized by loader)
__device__ float g_feat[NIMG * HW * C64];          // fp32 feats (rotate input)
__device__ float g_frot[NPAIR * HW * C64];         // rotated maps
__device__ float g_gx[NIMG * HW * COUT];           // raw conv out
__device__ __align__(16) char g_chB[NIMG * 128 * AIMGROW];  // bf16 hi, padded rows
__device__ __align__(16) char g_clB[NIMG * 128 * AIMGROW];  // bf16 lo
__device__ __align__(16) char g_wb[18 * BSTAGE];            // weights, stage blocks
__device__ __align__(16) char g_zpad[AIMGROW];              // zero page (stays 0)

// ===================== helpers ============================================
__device__ __forceinline__ uint32_t smem_u32(const void* p) {
    uint32_t a;
    asm("{ .reg .u64 t; cvta.to.shared.u64 t, %1; cvt.u32.u64 %0, t; }" : "=r"(a) : "l"(p));
    return a;
}
__device__ __forceinline__ void ldsm4(uint32_t* r, uint32_t a) {
    asm volatile("ldmatrix.sync.aligned.m8n8.x4.shared.b16 {%0,%1,%2,%3}, [%4];"
        : "=r"(r[0]), "=r"(r[1]), "=r"(r[2]), "=r"(r[3]) : "r"(a));
}
__device__ __forceinline__ void mma16816(float* d, const uint32_t* a, const uint32_t* b) {
    asm volatile("mma.sync.aligned.m16n8k16.row.col.f32.bf16.bf16.f32 "
        "{%0,%1,%2,%3}, {%4,%5,%6,%7}, {%8,%9}, {%0,%1,%2,%3};"
        : "+f"(d[0]), "+f"(d[1]), "+f"(d[2]), "+f"(d[3])
        : "r"(a[0]), "r"(a[1]), "r"(a[2]), "r"(a[3]), "r"(b[0]), "r"(b[1]));
}
__device__ __forceinline__ void mbar_init(uint32_t a, uint32_t c) {
    asm volatile("mbarrier.init.shared.b64 [%0], %1;" :: "r"(a), "r"(c) : "memory");
}
__device__ __forceinline__ void mbar_expect(uint32_t a, uint32_t bytes) {
    asm volatile("mbarrier.arrive.expect_tx.shared.b64 _, [%0], %1;"
                 :: "r"(a), "r"(bytes) : "memory");
}
__device__ __forceinline__ void bulk_g2s(uint32_t dst, const void* src, uint32_t bytes,
                                         uint32_t mbar) {
    asm volatile("cp.async.bulk.shared::cluster.global.mbarrier::complete_tx::bytes "
                 "[%0], [%1], %2, [%3];"
                 :: "r"(dst), "l"(src), "r"(bytes), "r"(mbar) : "memory");
}
__device__ __forceinline__ void mbar_wait(uint32_t a, uint32_t ph) {
    asm volatile(
        "{\n\t.reg .pred P;\n\tWL%=:\n\t"
        "mbarrier.try_wait.parity.acquire.cta.shared::cta.b64 P, [%0], %1, 0x989680;\n\t"
        "@P bra WD%=;\n\tbra WL%=;\n\tWD%=:\n\t}"
        :: "r"(a), "r"(ph) : "memory");
}

__device__ __forceinline__ void corners(float x, float y,
    int &xi0, int &xi1, int &yi0, int &yi1,
    float &w00, float &w10, float &w01, float &w11)
{
    float x0f = floorf(x), y0f = floorf(y);
    float fx = x - x0f, fy = y - y0f;
    float x1f = x0f + 1.0f, y1f = y0f + 1.0f;
    float vx0 = (x0f >= 0.0f && x0f <= 127.0f) ? 1.0f : 0.0f;
    float vx1 = (x1f >= 0.0f && x1f <= 127.0f) ? 1.0f : 0.0f;
    float vy0 = (y0f >= 0.0f && y0f <= 127.0f) ? 1.0f : 0.0f;
    float vy1 = (y1f >= 0.0f && y1f <= 127.0f) ? 1.0f : 0.0f;
    float wx0 = 1.0f - fx, wx1 = fx, wy0 = 1.0f - fy, wy1 = fy;
    w00 = wx0 * wy0 * vx0 * vy0;
    w10 = wx1 * wy0 * vx1 * vy0;
    w01 = wx0 * wy1 * vx0 * vy1;
    w11 = wx1 * wy1 * vx1 * vy1;
    xi0 = min(max((int)x0f, 0), 127);
    xi1 = min(max((int)x1f, 0), 127);
    yi0 = min(max((int)y0f, 0), 127);
    yi1 = min(max((int)y1f, 0), 127);
}

// ===================== prep kernels =======================================
// NCHW feats -> g_feat (NHWC fp32) + g_chB/g_clB ch0..63 (bf16 split)
__global__ void k_transpose(const float* __restrict__ feats)
{
    __shared__ float sm[64][65];
    int img = blockIdx.y;
    int px0 = blockIdx.x * 64;
    int tid = threadIdx.x;
    const float* src = feats + img * C64 * HW;
    #pragma unroll
    for (int k = 0; k < 16; k++) {
        int c = k * 4 + (tid >> 6);
        int p = tid & 63;
        sm[c][p] = src[c * HW + px0 + p];
    }
    __syncthreads();
    #pragma unroll
    for (int k = 0; k < 16; k++) {
        int p = k * 4 + (tid >> 6);
        int c = tid & 63;
        int px = px0 + p;
        float v = sm[c][p];
        g_feat[(img * HW + px) * C64 + c] = v;
        __nv_bfloat16 hi = __float2bfloat16_rn(v);
        size_t bo = (size_t)(img * HW + px) * AROWB + c * 2;
        *(__nv_bfloat16*)(g_chB + bo) = hi;
        *(__nv_bfloat16*)(g_clB + bo) = __float2bfloat16_rn(v - __bfloat162float(hi));
    }
}

// weights -> g_wb stage blocks: stage s = tap*2+kh: [hi|lo] x 192 oc x 144B
__global__ void k_wsplit(const float* __restrict__ wx)
{
    int idx = blockIdx.x * 256 + threadIdx.x;
    if (idx >= 18 * 192 * 64) return;
    int icl = idx % 64;
    int r   = idx / 64;
    int oc  = r % 192;
    int s   = r / 192;
    int kh = s & 1, tap = s >> 1;
    int ic = kh * 64 + icl;
    float v = wx[(oc * CIN + ic) * 9 + tap];
    __nv_bfloat16 hi = __float2bfloat16_rn(v);
    size_t off = (size_t)s * BSTAGE + (size_t)oc * BROWB + icl * 2;
    *(__nv_bfloat16*)(g_wb + off) = hi;
    *(__nv_bfloat16*)(g_wb + BSPLIT + off) = __float2bfloat16_rn(v - __bfloat162float(hi));
}

// ===================== warp stage (coalesced, 16 threads/pixel) ===========
__global__ void k_rotate(const float* __restrict__ trans)
{
    int p  = blockIdx.x;
    int b  = p / (AG * PR);
    int r  = p % (AG * PR);
    int i  = r / PR;
    int jj = r % PR;
    int j  = jj + (jj >= i ? 1 : 0);
    const float* t = trans + ((b * AG + i) * AG + j) * 16;
    float t00 = t[0], t01 = t[1], t10 = t[4], t11 = t[5];

    int lane = threadIdx.x & 15;
    int px = blockIdx.y * 16 + (threadIdx.x >> 4);
    int h = px >> 7, w = px & 127;
    float xs = (float)(2 * w + 1) * 0.0078125f - 1.0f;
    float ys = (float)(2 * h + 1) * 0.0078125f - 1.0f;
    float g0 = t00 * xs + t01 * ys;
    float g1 = t10 * xs + t11 * ys;
    float x = ((g0 + 1.0f) * 128.0f - 1.0f) * 0.5f;
    float y = ((g1 + 1.0f) * 128.0f - 1.0f) * 0.5f;

    int xi0, xi1, yi0, yi1; float w00, w10, w01, w11;
    corners(x, y, xi0, xi1, yi0, yi1, w00, w10, w01, w11);

    const float* base = g_feat + (size_t)(b * AG + j) * HW * C64 + lane * 4;
    float4 a  = *(const float4*)(base + (yi0 * 128 + xi0) * C64);
    float4 bb = *(const float4*)(base + (yi0 * 128 + xi1) * C64);
    float4 cc = *(const float4*)(base + (yi1 * 128 + xi0) * C64);
    float4 dd = *(const float4*)(base + (yi1 * 128 + xi1) * C64);
    float4 o;
    o.x = w00 * a.x + w10 * bb.x + w01 * cc.x + w11 * dd.x;
    o.y = w00 * a.y + w10 * bb.y + w01 * cc.y + w11 * dd.y;
    o.z = w00 * a.z + w10 * bb.z + w01 * cc.z + w11 * dd.z;
    o.w = w00 * a.w + w10 * bb.w + w01 * cc.w + w11 * dd.w;
    *(float4*)(g_frot + (size_t)(p * HW + px) * C64 + lane * 4) = o;
}

// translate + mean over j!=i -> bf16 split ch 64..127 of conv input
__global__ void k_translate(const float* __restrict__ trans)
{
    int bi = blockIdx.x;
    int i  = bi % AG;
    int lane = threadIdx.x & 15;
    int px = blockIdx.y * 16 + (threadIdx.x >> 4);
    int h = px >> 7, w = px & 127;
    float xsv = (float)(2 * w + 1) * 0.0078125f - 1.0f;
    float ysv = (float)(2 * h + 1) * 0.0078125f - 1.0f;

    float ax = 0.f, ay = 0.f, az = 0.f, aw = 0.f;
    #pragma unroll
    for (int jj = 0; jj < PR; jj++) {
        int j = jj + (jj >= i ? 1 : 0);
        const float* t = trans + (bi * AG + j) * 16;
        float xtr = (4.0f * t[3]) * 0.0078125f;
        float ytr = -(4.0f * t[7]) * 0.0078125f;
        float x = ((xsv + xtr + 1.0f) * 128.0f - 1.0f) * 0.5f;
        float y = ((ysv + ytr + 1.0f) * 128.0f - 1.0f) * 0.5f;
        int xi0, xi1, yi0, yi1; float w00, w10, w01, w11;
        corners(x, y, xi0, xi1, yi0, yi1, w00, w10, w01, w11);
        const float* fb = g_frot + (size_t)((bi * PR + jj) * HW) * C64 + lane * 4;
        float4 v00 = *(const float4*)(fb + (yi0 * 128 + xi0) * C64);
        float4 v10 = *(const float4*)(fb + (yi0 * 128 + xi1) * C64);
        float4 v01 = *(const float4*)(fb + (yi1 * 128 + xi0) * C64);
        float4 v11 = *(const float4*)(fb + (yi1 * 128 + xi1) * C64);
        ax += w00 * v00.x + w10 * v10.x + w01 * v01.x + w11 * v11.x;
        ay += w00 * v00.y + w10 * v10.y + w01 * v01.y + w11 * v11.y;
        az += w00 * v00.z + w10 * v10.z + w01 * v01.z + w11 * v11.z;
        aw += w00 * v00.w + w10 * v10.w + w01 * v01.w + w11 * v11.w;
    }
    float o[4] = {ax * 0.25f, ay * 0.25f, az * 0.25f, aw * 0.25f};
    size_t bo = (size_t)(bi * HW + px) * AROWB + (C64 + lane * 4) * 2;
    __nv_bfloat162 hi0, hi1, lo0, lo1;
    float h0 = __bfloat162float(__float2bfloat16_rn(o[0]));
    float h1 = __bfloat162float(__float2bfloat16_rn(o[1]));
    float h2 = __bfloat162float(__float2bfloat16_rn(o[2]));
    float h3 = __bfloat162float(__float2bfloat16_rn(o[3]));
    hi0 = __floats2bfloat162_rn(h0, h1); hi1 = __floats2bfloat162_rn(h2, h3);
    lo0 = __floats2bfloat162_rn(o[0] - h0, o[1] - h1);
    lo1 = __floats2bfloat162_rn(o[2] - h2, o[3] - h3);
    *(__nv_bfloat162*)(g_chB + bo)     = hi0;
    *(__nv_bfloat162*)(g_chB + bo + 4) = hi1;
    *(__nv_bfloat162*)(g_clB + bo)     = lo0;
    *(__nv_bfloat162*)(g_clB + bo + 4) = lo1;
}

// ===================== conv: mma.sync + cp.async.bulk pipeline ============
// CTA: one row (M=128 px) x N=192 oc. 18 stages (9 taps x 2 k-halves).
// SMEM: A hi/lo 130x272B (pad rows 0,129 zeroed); B double-buffered stages.
#define SA_H   0
#define SA_L   35360
#define SB_0   70720
#define SB_1   126016
#define SM_MB  181312          // mbA, mbB0, mbB1 (8B each)
#define SM_TOTAL 181344

__global__ void __launch_bounds__(256, 1) k_convmma()
{
    extern __shared__ char smem[];
    uint32_t sb = smem_u32(smem);
    int h   = blockIdx.x;
    int img = blockIdx.y;
    int tid = threadIdx.x;
    int wid = tid >> 5, lane = tid & 31;
    int mrow = wid & 3;            // 32-px group
    int ncol = wid >> 2;           // oc 0..95 / 96..191

    uint32_t mbA  = sb + SM_MB;
    uint32_t mbB0 = sb + SM_MB + 8;
    uint32_t mbB1 = sb + SM_MB + 16;

    // zero A pad rows (rows 0 and 129, both splits): 4 regions x 68 words
    for (int i = tid; i < 272; i += 256) {
        int rg = i / 68, wd = i % 68;
        uint32_t base = ((rg & 1) ? 129u * AROWB : 0u) + ((rg >> 1) ? (uint32_t)SA_L : (uint32_t)SA_H);
        *(uint32_t*)(smem + base + wd * 4) = 0u;
    }
    if (tid == 0) {
        mbar_init(mbA, 1); mbar_init(mbB0, 1); mbar_init(mbB1, 1);
        asm volatile("fence.proxy.async.shared::cta;" ::: "memory");
    }
    __syncthreads();
    if (tid == 0) {
        mbar_expect(mbB0, BSTAGE);
        bulk_g2s(sb + SB_0, g_wb, BSTAGE, mbB0);
    }

    float acc[2][12][4];
    #pragma unroll
    for (int mi = 0; mi < 2; mi++)
        #pragma unroll
        for (int ni = 0; ni < 12; ni++)
            #pragma unroll
            for (int k = 0; k < 4; k++) acc[mi][ni][k] = 0.0f;

    int brow[6];
    #pragma unroll
    for (int t = 0; t < 6; t++)
        brow[t] = ncol * 96 + t * 16 + ((lane >> 4) << 3) + (lane & 7);

    for (int s = 0; s < 18; s++) {
        int tap = s >> 1, kh = s & 1;
        int ky = tap / 3, kx = tap % 3;
        if ((s % 6) == 0) {
            if (s) __syncthreads();
            if (tid == 0) {
                int py = h - 1 + ky;
                bool v = (py >= 0 && py < 128);
                const char* sh = v ? (g_chB + (size_t)(img * 128 + py) * AIMGROW) : g_zpad;
                const char* sl = v ? (g_clB + (size_t)(img * 128 + py) * AIMGROW) : g_zpad;
                mbar_expect(mbA, 2 * AIMGROW);
                bulk_g2s(sb + SA_H + AROWB, sh, AIMGROW, mbA);
                bulk_g2s(sb + SA_L + AROWB, sl, AIMGROW, mbA);
            }
        }
        mbar_wait((s & 1) ? mbB1 : mbB0, (s >> 1) & 1);
        if ((s % 6) == 0) mbar_wait(mbA, ky & 1);
        __syncthreads();
        if (tid == 0 && s < 17) {
            uint32_t mb = ((s + 1) & 1) ? mbB1 : mbB0;
            mbar_expect(mb, BSTAGE);
            bulk_g2s(sb + (((s + 1) & 1) ? SB_1 : SB_0), g_wb + (size_t)(s + 1) * BSTAGE,
                     BSTAGE, mb);
        }

        uint32_t aH = sb + SA_H, aL = sb + SA_L;
        uint32_t bB = sb + ((s & 1) ? SB_1 : SB_0);
        int arow0 = mrow * 32 + kx + (lane & 15);
        #pragma unroll
        for (int ks = 0; ks < 4; ks++) {
            uint32_t Ah[2][4], Al[2][4];
            int ca = kh * 8 + 2 * ks + (lane >> 4);
            #pragma unroll
            for (int mi = 0; mi < 2; mi++) {
                uint32_t off = (uint32_t)(arow0 + mi * 16) * AROWB + ca * 16;
                ldsm4(Ah[mi], aH + off);
                ldsm4(Al[mi], aL + off);
            }
            int cb = 2 * ks + ((lane >> 3) & 1);
            #pragma unroll
            for (int t = 0; t < 6; t++) {
                uint32_t Bh[4], Bl[4];
                uint32_t boff = (uint32_t)brow[t] * BROWB + cb * 16;
                ldsm4(Bh, bB + boff);
                ldsm4(Bl, bB + BSPLIT + boff);
                #pragma unroll
                for (int mi = 0; mi < 2; mi++)
                    #pragma unroll
                    for (int hf = 0; hf < 2; hf++) {
                        float* d = acc[mi][2 * t + hf];
                        mma16816(d, Ah[mi], &Bh[2 * hf]);
                        mma16816(d, Al[mi], &Bh[2 * hf]);
                        mma16816(d, Ah[mi], &Bl[2 * hf]);
                    }
            }
        }
    }

    int imgrow = img * HW + h * 128;
    #pragma unroll
    for (int mi = 0; mi < 2; mi++) {
        int x0 = mrow * 32 + mi * 16 + (lane >> 2);
        #pragma unroll
        for (int ni = 0; ni < 12; ni++) {
            int oc = ncol * 96 + ni * 8 + (lane & 3) * 2;
            float* o0 = g_gx + (size_t)(imgrow + x0) * COUT + oc;
            float* o1 = g_gx + (size_t)(imgrow + x0 + 8) * COUT + oc;
            *(float2*)o0 = make_float2(acc[mi][ni][0], acc[mi][ni][1]);
            *(float2*)o1 = make_float2(acc[mi][ni][2], acc[mi][ni][3]);
        }
    }
}

// ===================== GRU gating =========================================
__global__ void k_gru(const float* __restrict__ bx, const float* __restrict__ bh,
                      float* __restrict__ out_nchw)
{
    int idx = blockIdx.x * 256 + threadIdx.x;
    int c = idx & 63;
    int t = idx >> 6;
    int px  = t & (HW - 1);
    int img = t >> 14;
    const float* g = g_gx + (size_t)t * COUT;
    float xr = g[c]       + bx[c]       + bh[c];
    float xz = g[64 + c]  + bx[64 + c]  + bh[64 + c];
    float xn = g[128 + c] + bx[128 + c];
    float rr = 1.0f / (1.0f + expf(-xr));
    float zz = 1.0f / (1.0f + expf(-xz));
    float nn = tanhf(xn + rr * bh[128 + c]);
    float o = (1.0f - zz) * nn;
    if (out_nchw) {
        out_nchw[(img * C64 + c) * HW + px] = o;
    } else {
        g_feat[(size_t)t * C64 + c] = o;
        __nv_bfloat16 hi = __float2bfloat16_rn(o);
        size_t bo = (size_t)t * AROWB + c * 2;
        *(__nv_bfloat16*)(g_chB + bo) = hi;
        *(__nv_bfloat16*)(g_clB + bo) = __float2bfloat16_rn(o - __bfloat162float(hi));
    }
}

// ==========================================================================
extern "C" void kernel_launch(void* const* d_in, const int* in_sizes, int n_in,
                              void* d_out, int out_size)
{
    (void)in_sizes; (void)n_in; (void)out_size;
    const float* feats = (const float*)d_in[0];
    const float* trans = (const float*)d_in[1];
    const float* wx    = (const float*)d_in[2];
    const float* bx    = (const float*)d_in[4];
    const float* bh    = (const float*)d_in[5];
    float* out = (float*)d_out;

    cudaFuncSetAttribute(k_convmma, cudaFuncAttributeMaxDynamicSharedMemorySize, SM_TOTAL);

    k_transpose<<<dim3(256, NIMG), 256>>>(feats);
    k_wsplit<<<(18 * 192 * 64 + 255) / 256, 256>>>(wx);

    // iteration 1
    k_rotate   <<<dim3(NPAIR, 1024), 256>>>(trans);
    k_translate<<<dim3(NIMG, 1024), 256>>>(trans);
    k_convmma  <<<dim3(128, NIMG), 256, SM_TOTAL>>>();
    k_gru      <<<(NIMG * HW * C64) / 256, 256>>>(bx, bh, nullptr);

    // iteration 2
    k_rotate   <<<dim3(NPAIR, 1024), 256>>>(trans);
    k_translate<<<dim3(NIMG, 1024), 256>>>(trans);
    k_convmma  <<<dim3(128, NIMG), 256, SM_TOTAL>>>();
    k_gru      <<<(NIMG * HW * C64) / 256, 256>>>(bx, bh, out);
}